// round 5
// baseline (speedup 1.0000x reference)
#include <cuda_runtime.h>

#define BB      64
#define DD      3072
#define NTRAIN  50000
#define NPAD    50176          // 196*256, = 49*1024
#define NSPLIT  49
#define CHUNK   1024

// ---------- device scratch (no allocation allowed) ----------
__device__ float g_score[BB * NPAD];            // scores [b][i]
__device__ float g_wT[NPAD * BB];               // softmax weights transposed [i][b]
__device__ float g_coef[BB * 4];
__device__ float g_stats[BB * 2];
__device__ float g_partial[NSPLIT * BB * DD];   // split-K partials

typedef unsigned long long u64;

__device__ __forceinline__ void fma2(u64 &d, u64 a, u64 b) {
    asm("fma.rn.f32x2 %0, %1, %2, %0;" : "+l"(d) : "l"(a), "l"(b));
}
__device__ __forceinline__ u64 pack2(float lo, float hi) {
    u64 r; asm("mov.b64 %0, {%1, %2};" : "=l"(r) : "f"(lo), "f"(hi)); return r;
}

// ---------- per-row coefficients ----------
__global__ void k_setup(const float* __restrict__ acp, const int* __restrict__ t) {
    int b = threadIdx.x;
    if (b < BB) {
        float ac = acp[t[b]];
        float a  = sqrtf(ac);
        float om = 1.0f - ac;
        float is = rsqrtf(om);
        g_coef[b*4+0] = a / om;             // coef on cross
        g_coef[b*4+1] = -ac / (2.0f * om);  // coef on ||x0||^2
        g_coef[b*4+2] = is;                 // coef_x
        g_coef[b*4+3] = a * is;             // coef_x_hat
    }
}

// ---------- phase 1: cross GEMM + train sumsq + score ----------
// block: 64(b) x 96(i), K-step 32. thread tile 4b x 6i, FFMA2 over k-pairs.
#define TN 96
#define P1B ((NTRAIN + TN - 1) / TN)   // 521
#define XS 34

__global__ __launch_bounds__(256, 2)
void k_phase1(const float* __restrict__ x, const float* __restrict__ train) {
    __shared__ __align__(16) float xs[64 * XS];
    __shared__ __align__(16) float trs[TN * XS];
    __shared__ float strsq[TN];

    int tid = threadIdx.x;
    int tx  = tid & 15;     // b = tx + 16e
    int ty  = tid >> 4;     // i = ty*6 + f
    int i0  = blockIdx.x * TN;

    u64 acc[4][6];
    #pragma unroll
    for (int e = 0; e < 4; e++)
        #pragma unroll
        for (int f = 0; f < 6; f++) acc[e][f] = 0ull;
    float tacc[3] = {0.f, 0.f, 0.f};

    for (int k0 = 0; k0 < DD; k0 += 32) {
        #pragma unroll
        for (int q = 0; q < 2; q++) {
            int idx = q * 256 + tid;
            int b = idx >> 3, kq = idx & 7;
            float4 v = *(const float4*)&x[b * DD + k0 + kq * 4];
            *(float2*)&xs[b * XS + kq*4]   = make_float2(v.x, v.y);
            *(float2*)&xs[b * XS + kq*4+2] = make_float2(v.z, v.w);
        }
        #pragma unroll
        for (int q = 0; q < 3; q++) {
            int idx = q * 256 + tid;
            int i = idx >> 3, kq = idx & 7;
            int gi = i0 + i;
            float4 v = make_float4(0.f, 0.f, 0.f, 0.f);
            if (gi < NTRAIN) v = *(const float4*)&train[(long long)gi * DD + k0 + kq * 4];
            *(float2*)&trs[i * XS + kq*4]   = make_float2(v.x, v.y);
            *(float2*)&trs[i * XS + kq*4+2] = make_float2(v.z, v.w);
            tacc[q] += v.x*v.x + v.y*v.y + v.z*v.z + v.w*v.w;
        }
        __syncthreads();
        #pragma unroll
        for (int kk = 0; kk < 32; kk += 2) {
            u64 xp[4], tp[6];
            #pragma unroll
            for (int e = 0; e < 4; e++)
                xp[e] = *(const u64*)&xs[(tx + 16*e) * XS + kk];
            #pragma unroll
            for (int f = 0; f < 6; f++)
                tp[f] = *(const u64*)&trs[(ty*6 + f) * XS + kk];
            #pragma unroll
            for (int e = 0; e < 4; e++)
                #pragma unroll
                for (int f = 0; f < 6; f++) fma2(acc[e][f], xp[e], tp[f]);
        }
        __syncthreads();
    }

    // reduce per-train-row sumsq (8 loader lanes per row), reuse trs
    #pragma unroll
    for (int q = 0; q < 3; q++) {
        int idx = q * 256 + tid;
        trs[(idx >> 3) * 8 + (idx & 7)] = tacc[q];
    }
    __syncthreads();
    if (tid < TN) {
        float s = 0.f;
        #pragma unroll
        for (int j = 0; j < 8; j++) s += trs[tid * 8 + j];
        strsq[tid] = s;
    }
    __syncthreads();

    // score = (a/om)*cross - (a^2/(2om))*||x0||^2  (row-constant term dropped)
    #pragma unroll
    for (int e = 0; e < 4; e++) {
        int b = tx + 16*e;
        float aoo = g_coef[b*4+0];
        float c2  = g_coef[b*4+1];
        #pragma unroll
        for (int f = 0; f < 6; f++) {
            int gi = i0 + ty*6 + f;
            if (gi < NTRAIN) {
                float2 a2 = *(float2*)&acc[e][f];
                g_score[b * NPAD + gi] = aoo * (a2.x + a2.y) + c2 * strsq[ty*6 + f];
            }
        }
    }
}

// ---------- phase 2a: per-row max + sumexp ----------
__global__ void k_rowstats() {
    __shared__ float red[256];
    int b = blockIdx.x, tid = threadIdx.x;
    const float* s = &g_score[b * NPAD];

    float mx = -3.4e38f;
    for (int i = tid; i < NTRAIN; i += 256) mx = fmaxf(mx, s[i]);
    red[tid] = mx; __syncthreads();
    for (int st = 128; st > 0; st >>= 1) {
        if (tid < st) red[tid] = fmaxf(red[tid], red[tid + st]);
        __syncthreads();
    }
    mx = red[0]; __syncthreads();

    float sum = 0.f;
    for (int i = tid; i < NTRAIN; i += 256) sum += __expf(s[i] - mx);
    red[tid] = sum; __syncthreads();
    for (int st = 128; st > 0; st >>= 1) {
        if (tid < st) red[tid] += red[tid + st];
        __syncthreads();
    }
    if (tid == 0) { g_stats[b*2] = mx; g_stats[b*2+1] = 1.0f / red[0]; }
}

// ---------- phase 2b: weights, written transposed [i][b] ----------
__global__ void k_weights() {
    int b = blockIdx.y;
    int i = blockIdx.x * 256 + threadIdx.x;
    float mx = g_stats[b*2], inv = g_stats[b*2+1];
    float w = (i < NTRAIN) ? __expf(g_score[b * NPAD + i] - mx) * inv : 0.f;
    g_wT[(long long)i * BB + b] = w;
}

// ---------- phase 3: weighted = w @ train, split-K partials ----------
// block: 64(b) x 128(d) over CHUNK k-rows. thread tile 4b x 4 d-pairs.
__global__ __launch_bounds__(256, 2)
void k_phase3(const float* __restrict__ train) {
    __shared__ __align__(16) float trs[32 * 128];
    __shared__ __align__(16) float ws[32 * 64];

    int tid  = threadIdx.x;
    int dgrp = tid & 15;            // d-pairs at 2*dgrp + 32*p
    int bgrp = tid >> 4;            // b = bgrp*4 + j
    int d0   = blockIdx.x * 128;
    int kbeg = blockIdx.y * CHUNK;

    u64 acc[4][4];
    #pragma unroll
    for (int j = 0; j < 4; j++)
        #pragma unroll
        for (int p = 0; p < 4; p++) acc[j][p] = 0ull;

    for (int k0 = 0; k0 < CHUNK; k0 += 32) {
        // train tile 32 x 128 (coalesced)
        #pragma unroll
        for (int q = 0; q < 4; q++) {
            int idx = q * 256 + tid;
            int kk = idx >> 5, c4 = idx & 31;
            int gi = kbeg + k0 + kk;
            float4 v = make_float4(0.f, 0.f, 0.f, 0.f);
            if (gi < NTRAIN) v = *(const float4*)&train[(long long)gi * DD + d0 + c4*4];
            *(float4*)&trs[kk * 128 + c4*4] = v;
        }
        // w tile 32 x 64 from transposed layout (coalesced)
        #pragma unroll
        for (int q = 0; q < 2; q++) {
            int idx = q * 256 + tid;
            *(float4*)&ws[idx * 4] = *(const float4*)&g_wT[(long long)(kbeg + k0) * BB + idx * 4];
        }
        __syncthreads();
        #pragma unroll
        for (int kk = 0; kk < 32; kk++) {
            u64 wp[4], tp[4];
            #pragma unroll
            for (int j = 0; j < 4; j++) {
                float w = ws[kk * 64 + bgrp*4 + j];
                wp[j] = pack2(w, w);
            }
            #pragma unroll
            for (int p = 0; p < 4; p++)
                tp[p] = *(const u64*)&trs[kk * 128 + 2*dgrp + 32*p];
            #pragma unroll
            for (int j = 0; j < 4; j++)
                #pragma unroll
                for (int p = 0; p < 4; p++) fma2(acc[j][p], wp[j], tp[p]);
        }
        __syncthreads();
    }

    float* out = &g_partial[(long long)blockIdx.y * BB * DD];
    #pragma unroll
    for (int j = 0; j < 4; j++) {
        int b = bgrp*4 + j;
        #pragma unroll
        for (int p = 0; p < 4; p++)
            *(float2*)&out[b * DD + d0 + 2*dgrp + 32*p] = *(float2*)&acc[j][p];
    }
}

// ---------- phase 4: combine ----------
__global__ void k_combine(const float* __restrict__ x, float* __restrict__ out) {
    int b = blockIdx.y;
    int d = blockIdx.x * 256 + threadIdx.x;
    float p = 0.f;
    #pragma unroll 7
    for (int s = 0; s < NSPLIT; s++) p += g_partial[(long long)s * BB * DD + b * DD + d];
    float cx = g_coef[b*4+2], ch = g_coef[b*4+3];
    out[b * DD + d] = cx * x[b * DD + d] - ch * p;
}

extern "C" void kernel_launch(void* const* d_in, const int* in_sizes, int n_in,
                              void* d_out, int out_size) {
    const float* x     = (const float*)d_in[0];
    const float* train = (const float*)d_in[1];
    const float* acp   = (const float*)d_in[2];
    const int*   t     = (const int*)d_in[3];
    float* out = (float*)d_out;

    k_setup<<<1, 64>>>(acp, t);
    k_phase1<<<P1B, 256>>>(x, train);
    k_rowstats<<<BB, 256>>>();
    k_weights<<<dim3(NPAD / 256, BB), 256>>>();
    k_phase3<<<dim3(DD / 128, NSPLIT), 256>>>(train);
    k_combine<<<dim3(DD / 256, BB), 256>>>(x, out);
}